// round 1
// baseline (speedup 1.0000x reference)
#include <cuda_runtime.h>
#include <math.h>

#define B_   16
#define T_   36
#define NN_  207
#define D_   64
#define H_   8
#define DPH_ 8
#define LNEPS 1e-5f

// Shared layout (floats):
// sQ  [36][65]  raw Q tile      (stride 65: odd -> conflict-free column walks)
// sK  [36][65]  raw K tile
// sV  [36][65]  raw V tile
// sVh [36][68]  projected V     (stride 68: float4-aligned rows)
// sQh [36][68]  conv(Q) feats   (reused as sOut at the end)
// sKh [36][68]  conv(K) feats
// sS  [36][40]  scores / probs
// sCtx[36][68]  attention context accumulator (all heads)
// sWT [64][68]  Wv^T, later Wo^T (transposed for float4 reads)
// sWq [64][25]  conv_q weights (padded stride 25: conflict-free per-c reads)
// sWk [64][25]
// sVec[6*64]    bq, bk, bv, bo, gamma, beta

#define OFF_Q   0
#define OFF_K   (OFF_Q   + 36*65)
#define OFF_V   (OFF_K   + 36*65)
#define OFF_VH  (OFF_V   + 36*65)
#define OFF_QH  (OFF_VH  + 36*68)
#define OFF_KH  (OFF_QH  + 36*68)
#define OFF_S   (OFF_KH  + 36*68)
#define OFF_CTX (OFF_S   + 36*40)
#define OFF_WT  (OFF_CTX + 36*68)
#define OFF_WQ  (OFF_WT  + 64*68)
#define OFF_WK  (OFF_WQ  + 64*25)
#define OFF_VEC (OFF_WK  + 64*25)
#define SMEM_FLOATS (OFF_VEC + 6*64)
#define SMEM_BYTES  (SMEM_FLOATS * 4)

__global__ __launch_bounds__(256) void fused_attn_kernel(
    const float* __restrict__ X,  const float* __restrict__ Q,
    const float* __restrict__ K,  const float* __restrict__ V,
    const float* __restrict__ Wv, const float* __restrict__ bv,
    const float* __restrict__ Wo, const float* __restrict__ bo,
    const float* __restrict__ cqw, const float* __restrict__ cqb,
    const float* __restrict__ ckw, const float* __restrict__ ckb,
    const float* __restrict__ gamma, const float* __restrict__ beta,
    float* __restrict__ Out)
{
    extern __shared__ float sm[];
    float* sQ   = sm + OFF_Q;
    float* sK   = sm + OFF_K;
    float* sV   = sm + OFF_V;
    float* sVh  = sm + OFF_VH;
    float* sQh  = sm + OFF_QH;
    float* sKh  = sm + OFF_KH;
    float* sS   = sm + OFF_S;
    float* sCtx = sm + OFF_CTX;
    float* sWT  = sm + OFF_WT;
    float* sWq  = sm + OFF_WQ;
    float* sWk  = sm + OFF_WK;
    float* sVec = sm + OFF_VEC;

    const int tid = threadIdx.x;
    const int bn  = blockIdx.x;
    const int bb  = bn / NN_;
    const int nn  = bn - bb * NN_;
    const int base    = ((bb * T_) * NN_ + nn) * D_;   // (b, t=0, n, c=0)
    const int rstride = NN_ * D_;                       // stride between t rows

    // ---------------- Phase 0: cooperative loads ----------------
    for (int i = tid; i < T_ * 16; i += 256) {
        const int t  = i >> 4;
        const int c4 = (i & 15) * 4;
        const float4 q4 = *(const float4*)(Q + base + t * rstride + c4);
        const float4 k4 = *(const float4*)(K + base + t * rstride + c4);
        const float4 v4 = *(const float4*)(V + base + t * rstride + c4);
        float* dq = sQ + t * 65 + c4;
        dq[0] = q4.x; dq[1] = q4.y; dq[2] = q4.z; dq[3] = q4.w;
        float* dk = sK + t * 65 + c4;
        dk[0] = k4.x; dk[1] = k4.y; dk[2] = k4.z; dk[3] = k4.w;
        float* dv = sV + t * 65 + c4;
        dv[0] = v4.x; dv[1] = v4.y; dv[2] = v4.z; dv[3] = v4.w;
    }
    // Wv transposed into sWT: sWT[k][r] = Wv[r][k]
    for (int i = tid; i < 64 * 16; i += 256) {
        const int r  = i >> 4;
        const int c4 = (i & 15) * 4;
        const float4 w = *(const float4*)(Wv + r * 64 + c4);
        sWT[(c4 + 0) * 68 + r] = w.x;
        sWT[(c4 + 1) * 68 + r] = w.y;
        sWT[(c4 + 2) * 68 + r] = w.z;
        sWT[(c4 + 3) * 68 + r] = w.w;
    }
    // conv weights (C,dph,1,3) flat -> padded stride 25
    for (int i = tid; i < 64 * 24; i += 256) {
        const int c = i / 24;
        const int j = i - c * 24;
        sWq[c * 25 + j] = cqw[i];
        sWk[c * 25 + j] = ckw[i];
    }
    if (tid < 64) {
        sVec[tid]       = cqb[tid];
        sVec[64  + tid] = ckb[tid];
        sVec[128 + tid] = bv[tid];
        sVec[192 + tid] = bo[tid];
        sVec[256 + tid] = gamma[tid];
        sVec[320 + tid] = beta[tid];
    }
    for (int i = tid; i < T_ * 68; i += 256) sCtx[i] = 0.0f;
    __syncthreads();

    // ---------------- Phase 1: Vh = V @ Wv^T + bv ----------------
    for (int i = tid; i < T_ * 16; i += 256) {
        const int t  = i >> 4;
        const int c0 = (i & 15) * 4;
        float4 acc = *(const float4*)(sVec + 128 + c0);
        #pragma unroll 8
        for (int k = 0; k < 64; ++k) {
            const float  v = sV[t * 65 + k];
            const float4 w = *(const float4*)(sWT + k * 68 + c0);
            acc.x = fmaf(v, w.x, acc.x);
            acc.y = fmaf(v, w.y, acc.y);
            acc.z = fmaf(v, w.z, acc.z);
            acc.w = fmaf(v, w.w, acc.w);
        }
        *(float4*)(sVh + t * 68 + c0) = acc;
    }
    __syncthreads();

    // ---------------- Phase 2: per-head attention ----------------
    for (int h = 0; h < H_; ++h) {
        const int col = h * DPH_;
        // ---- causal conv over T: thread = (c, sel(Q/K), t-half) ----
        {
            const int c    = tid & 63;
            const int sel  = (tid >> 6) & 1;
            const int half = tid >> 7;
            const int t0   = half * 18;
            const float* wp  = (sel ? sWk : sWq) + c * 25;
            const float* src = sel ? sK : sQ;
            float*       dst = sel ? sKh : sQh;
            const float bias = sVec[sel * 64 + c];

            float wr[24];
            #pragma unroll
            for (int j = 0; j < 24; ++j) wr[j] = wp[j];

            float a0[8], a1[8];
            #pragma unroll
            for (int i2 = 0; i2 < 8; ++i2) {
                a0[i2] = (t0 >= 2) ? src[(t0 - 2) * 65 + col + i2] : 0.0f;
                a1[i2] = (t0 >= 1) ? src[(t0 - 1) * 65 + col + i2] : 0.0f;
            }
            #pragma unroll
            for (int tt = 0; tt < 18; ++tt) {
                const int t = t0 + tt;
                float acc = bias;
                #pragma unroll
                for (int i2 = 0; i2 < 8; ++i2) {
                    const float a2 = src[t * 65 + col + i2];
                    acc = fmaf(wr[i2 * 3 + 0], a0[i2], acc);
                    acc = fmaf(wr[i2 * 3 + 1], a1[i2], acc);
                    acc = fmaf(wr[i2 * 3 + 2], a2,     acc);
                    a0[i2] = a1[i2];
                    a1[i2] = a2;
                }
                dst[t * 68 + c] = acc;
            }
        }
        __syncthreads();

        // ---- scores: S[q][k] = 0.125 * Qh[q]·Kh[k], lower triangle ----
        for (int i = tid; i < T_ * T_; i += 256) {
            const int q = i / 36;
            const int k = i - q * 36;
            if (k > q) continue;
            float ax = 0.f, ay = 0.f, az = 0.f, aw = 0.f;
            #pragma unroll 4
            for (int c0 = 0; c0 < 64; c0 += 4) {
                const float4 qv = *(const float4*)(sQh + q * 68 + c0);
                const float4 kv = *(const float4*)(sKh + k * 68 + c0);
                ax = fmaf(qv.x, kv.x, ax);
                ay = fmaf(qv.y, kv.y, ay);
                az = fmaf(qv.z, kv.z, az);
                aw = fmaf(qv.w, kv.w, aw);
            }
            sS[q * 40 + k] = (ax + ay + az + aw) * 0.125f;
        }
        __syncthreads();

        // ---- softmax per row (causal length q+1), warp per row ----
        {
            const int warp = tid >> 5, lane = tid & 31;
            for (int q = warp; q < T_; q += 8) {
                float m = -1e30f;
                for (int k = lane; k <= q; k += 32) m = fmaxf(m, sS[q * 40 + k]);
                #pragma unroll
                for (int o = 16; o; o >>= 1) m = fmaxf(m, __shfl_xor_sync(0xffffffffu, m, o));
                float ssum = 0.0f;
                for (int k = lane; k <= q; k += 32) {
                    const float e = __expf(sS[q * 40 + k] - m);
                    sS[q * 40 + k] = e;
                    ssum += e;
                }
                #pragma unroll
                for (int o = 16; o; o >>= 1) ssum += __shfl_xor_sync(0xffffffffu, ssum, o);
                const float inv = 1.0f / ssum;
                for (int k = lane; k <= q; k += 32) sS[q * 40 + k] *= inv;
            }
        }
        __syncthreads();

        // ---- ctx[q][h*8+e] += sum_{k<=q} P[q][k] * Vh[k][h*8+e] ----
        for (int i = tid; i < T_ * DPH_; i += 256) {
            const int q = i >> 3;
            const int e = i & 7;
            const int cc = col + e;
            float acc = 0.0f;
            for (int k = 0; k <= q; ++k)
                acc = fmaf(sS[q * 40 + k], sVh[k * 68 + cc], acc);
            sCtx[q * 68 + cc] += acc;
        }
        __syncthreads();
    }

    // ---------------- Phase 3: load Wo^T (overwrites Wv^T) ----------------
    for (int i = tid; i < 64 * 16; i += 256) {
        const int r  = i >> 4;
        const int c4 = (i & 15) * 4;
        const float4 w = *(const float4*)(Wo + r * 64 + c4);
        sWT[(c4 + 0) * 68 + r] = w.x;
        sWT[(c4 + 1) * 68 + r] = w.y;
        sWT[(c4 + 2) * 68 + r] = w.z;
        sWT[(c4 + 3) * 68 + r] = w.w;
    }
    __syncthreads();

    // ---------------- Phase 4: out = ctx @ Wo^T + bo + X ----------------
    float* sOut = sQh;  // reuse
    for (int i = tid; i < T_ * 16; i += 256) {
        const int t  = i >> 4;
        const int c0 = (i & 15) * 4;
        float4 acc = *(const float4*)(sVec + 192 + c0);
        #pragma unroll 8
        for (int e = 0; e < 64; ++e) {
            const float  cv = sCtx[t * 68 + e];
            const float4 w  = *(const float4*)(sWT + e * 68 + c0);
            acc.x = fmaf(cv, w.x, acc.x);
            acc.y = fmaf(cv, w.y, acc.y);
            acc.z = fmaf(cv, w.z, acc.z);
            acc.w = fmaf(cv, w.w, acc.w);
        }
        const float4 x = *(const float4*)(X + base + t * rstride + c0);
        acc.x += x.x; acc.y += x.y; acc.z += x.z; acc.w += x.w;
        *(float4*)(sOut + t * 68 + c0) = acc;
    }
    __syncthreads();

    // ---------------- Phase 5: LayerNorm + store ----------------
    {
        const int warp = tid >> 5, lane = tid & 31;
        for (int t = warp; t < T_; t += 8) {
            const float x0 = sOut[t * 68 + lane];
            const float x1 = sOut[t * 68 + 32 + lane];
            float s  = x0 + x1;
            float s2 = x0 * x0 + x1 * x1;
            #pragma unroll
            for (int o = 16; o; o >>= 1) {
                s  += __shfl_xor_sync(0xffffffffu, s,  o);
                s2 += __shfl_xor_sync(0xffffffffu, s2, o);
            }
            const float mu   = s * (1.0f / 64.0f);
            const float var  = s2 * (1.0f / 64.0f) - mu * mu;
            const float rstd = rsqrtf(var + LNEPS);
            float* outp = Out + base + t * rstride;
            outp[lane]      = (x0 - mu) * rstd * sVec[256 + lane]      + sVec[320 + lane];
            outp[32 + lane] = (x1 - mu) * rstd * sVec[256 + 32 + lane] + sVec[320 + 32 + lane];
        }
    }
}

extern "C" void kernel_launch(void* const* d_in, const int* in_sizes, int n_in,
                              void* d_out, int out_size) {
    (void)in_sizes; (void)n_in; (void)out_size;
    cudaFuncSetAttribute(fused_attn_kernel,
                         cudaFuncAttributeMaxDynamicSharedMemorySize, SMEM_BYTES);
    fused_attn_kernel<<<B_ * NN_, 256, SMEM_BYTES>>>(
        (const float*)d_in[0],  (const float*)d_in[1],
        (const float*)d_in[2],  (const float*)d_in[3],
        (const float*)d_in[4],  (const float*)d_in[5],
        (const float*)d_in[6],  (const float*)d_in[7],
        (const float*)d_in[8],  (const float*)d_in[9],
        (const float*)d_in[10], (const float*)d_in[11],
        (const float*)d_in[12], (const float*)d_in[13],
        (float*)d_out);
}

// round 2
// speedup vs baseline: 1.7073x; 1.7073x over previous
#include <cuda_runtime.h>
#include <math.h>

#define B_   16
#define T_   36
#define NN_  207
#define D_   64
#define H_   8
#define LNEPS 1e-5f

// Block-invariant fused conv->score matrices (computed by setup_kernel):
//   gM[j][c'] (stride 28): c'<24 : (Wq^T Wk)[j][c'],  c'==24 : (Wq^T bk)[j],  c'>24 : 0
//   gVv[j] = (Wk^T bq)[j],  gVv[24] = bq . bk
__device__ float gM[24 * 28];
__device__ float gVv[25];

__global__ void setup_kernel(const float* __restrict__ cqw, const float* __restrict__ cqb,
                             const float* __restrict__ ckw, const float* __restrict__ ckb)
{
    const int i = threadIdx.x;
    if (i < 672) {
        const int j  = i / 28;
        const int c2 = i - j * 28;
        float acc = 0.f;
        if (c2 < 24) {
            for (int c = 0; c < 64; ++c) acc = fmaf(cqw[c * 24 + j], ckw[c * 24 + c2], acc);
        } else if (c2 == 24) {
            for (int c = 0; c < 64; ++c) acc = fmaf(cqw[c * 24 + j], ckb[c], acc);
        }
        gM[i] = acc;
    }
    if (i < 24) {
        float a = 0.f;
        for (int c = 0; c < 64; ++c) a = fmaf(ckw[c * 24 + i], cqb[c], a);
        gVv[i] = a;
    }
    if (i == 0) {
        float a = 0.f;
        for (int c = 0; c < 64; ++c) a = fmaf(cqb[c], ckb[c], a);
        gVv[24] = a;
    }
}

// Shared layout (floats):
#define OFF_Q    0                    // [36][65] raw Q
#define OFF_K    (OFF_Q + 36*65)      // [36][65] raw K
#define OFF_V    (OFF_K + 36*65)      // [36][65] raw V  (dead after phase 1)
#define OFF_AM   OFF_V                // [36][28] A windows  (overlays sV)
#define OFF_BM   (OFF_AM + 36*28)     // [36][28] B windows (+col24=1, col25..27=0)
#define OFF_VH   (OFF_V + 36*65)      // [36][68] projected V; later out buffer
#define OFF_CTX  (OFF_VH + 36*68)     // [36][68] context accumulator
#define OFF_S    (OFF_CTX + 36*68)    // [36][40] scores/probs
#define OFF_WT   (OFF_S + 36*40)      // [64][68] Wv^T (phase1) / Wo^T (phase4)
#define OFF_M    OFF_WT               // [24][28] M|u       (overlays sWT in head loop)
#define OFF_P    (OFF_M + 24*28)      // [36][28] P = Am @ (M|u)
#define OFF_VEC  (OFF_WT + 64*68)     // bv(64) bo(64) gamma(64) beta(64)
#define OFF_VV   (OFF_VEC + 256)      // [25] v vector + c0
#define OFF_CK   (OFF_VV + 28)        // [36] per-k additive score term
#define SMEM_FLOATS (OFF_CK + 36)
#define SMEM_BYTES  (SMEM_FLOATS * 4)

__global__ __launch_bounds__(256, 3) void fused_attn_kernel(
    const float* __restrict__ X,  const float* __restrict__ Q,
    const float* __restrict__ K,  const float* __restrict__ V,
    const float* __restrict__ Wv, const float* __restrict__ bv,
    const float* __restrict__ Wo, const float* __restrict__ bo,
    const float* __restrict__ gamma, const float* __restrict__ beta,
    float* __restrict__ Out)
{
    extern __shared__ float sm[];
    float* sQ   = sm + OFF_Q;
    float* sK   = sm + OFF_K;
    float* sV   = sm + OFF_V;
    float* sAm  = sm + OFF_AM;
    float* sBm  = sm + OFF_BM;
    float* sVh  = sm + OFF_VH;
    float* sCtx = sm + OFF_CTX;
    float* sS   = sm + OFF_S;
    float* sWT  = sm + OFF_WT;
    float* sM   = sm + OFF_M;
    float* sP   = sm + OFF_P;
    float* sVec = sm + OFF_VEC;
    float* sVv  = sm + OFF_VV;
    float* sCk  = sm + OFF_CK;

    const int tid = threadIdx.x;
    const int bn  = blockIdx.x;
    const int bb  = bn / NN_;
    const int nn  = bn - bb * NN_;
    const int base    = ((bb * T_) * NN_ + nn) * D_;
    const int rstride = NN_ * D_;

    // ---------------- Phase 0: cooperative loads ----------------
    for (int i = tid; i < T_ * 16; i += 256) {
        const int t  = i >> 4;
        const int c4 = (i & 15) * 4;
        const float4 q4 = *(const float4*)(Q + base + t * rstride + c4);
        const float4 k4 = *(const float4*)(K + base + t * rstride + c4);
        const float4 v4 = *(const float4*)(V + base + t * rstride + c4);
        float* dq = sQ + t * 65 + c4;
        dq[0] = q4.x; dq[1] = q4.y; dq[2] = q4.z; dq[3] = q4.w;
        float* dk = sK + t * 65 + c4;
        dk[0] = k4.x; dk[1] = k4.y; dk[2] = k4.z; dk[3] = k4.w;
        float* dv = sV + t * 65 + c4;
        dv[0] = v4.x; dv[1] = v4.y; dv[2] = v4.z; dv[3] = v4.w;
    }
    for (int i = tid; i < 64 * 16; i += 256) {       // Wv^T
        const int r  = i >> 4;
        const int c4 = (i & 15) * 4;
        const float4 w = *(const float4*)(Wv + r * 64 + c4);
        sWT[(c4 + 0) * 68 + r] = w.x;
        sWT[(c4 + 1) * 68 + r] = w.y;
        sWT[(c4 + 2) * 68 + r] = w.z;
        sWT[(c4 + 3) * 68 + r] = w.w;
    }
    if (tid < 64) {
        sVec[tid]       = bv[tid];
        sVec[64  + tid] = bo[tid];
        sVec[128 + tid] = gamma[tid];
        sVec[192 + tid] = beta[tid];
    }
    for (int i = tid; i < T_ * 68; i += 256) sCtx[i] = 0.0f;
    __syncthreads();

    // ---------------- Phase 1: Vh = V @ Wv^T + bv  (2-row tiled) ----------------
    for (int i = tid; i < 18 * 16; i += 256) {
        const int t  = (i >> 4) * 2;
        const int c0 = (i & 15) * 4;
        const float4 b4 = *(const float4*)(sVec + c0);
        float4 a0 = b4, a1 = b4;
        #pragma unroll 8
        for (int k = 0; k < 64; ++k) {
            const float4 w  = *(const float4*)(sWT + k * 68 + c0);
            const float  v0 = sV[t * 65 + k];
            const float  v1 = sV[(t + 1) * 65 + k];
            a0.x = fmaf(v0, w.x, a0.x); a0.y = fmaf(v0, w.y, a0.y);
            a0.z = fmaf(v0, w.z, a0.z); a0.w = fmaf(v0, w.w, a0.w);
            a1.x = fmaf(v1, w.x, a1.x); a1.y = fmaf(v1, w.y, a1.y);
            a1.z = fmaf(v1, w.z, a1.z); a1.w = fmaf(v1, w.w, a1.w);
        }
        *(float4*)(sVh + t * 68 + c0)       = a0;
        *(float4*)(sVh + (t + 1) * 68 + c0) = a1;
    }
    __syncthreads();

    // ---------------- Phase 2: per-head attention ----------------
    for (int h = 0; h < H_; ++h) {
        const int col = h * 8;

        // -- (a) build A/B window matrices (+ load M on first head) --
        if (h == 0) {
            for (int i = tid; i < 672; i += 256) sM[i] = gM[i];
            if (tid < 25) sVv[tid] = gVv[tid];
        }
        for (int i = tid; i < 36 * 24; i += 256) {
            const int t   = i / 24;
            const int j   = i - t * 24;
            const int i2  = j / 3;
            const int tap = j - i2 * 3;
            const int tp  = t + tap - 2;
            float qv = 0.f, kv = 0.f;
            if (tp >= 0) {
                qv = sQ[tp * 65 + col + i2];
                kv = sK[tp * 65 + col + i2];
            }
            sAm[t * 28 + j] = qv;
            sBm[t * 28 + j] = kv;
        }
        if (tid < 36) {
            float* b = sBm + tid * 28;
            b[24] = 1.0f; b[25] = 0.0f; b[26] = 0.0f; b[27] = 0.0f;
        }
        __syncthreads();

        // -- (b) P = Am @ (M|u)  (36 x 28), and per-k term ck --
        if (tid < 252) {
            const int t  = tid / 7;
            const int c4 = (tid - t * 7) * 4;
            float4 acc = make_float4(0.f, 0.f, 0.f, 0.f);
            const float* am = sAm + t * 28;
            #pragma unroll 6
            for (int j = 0; j < 24; ++j) {
                const float  a = am[j];
                const float4 m = *(const float4*)(sM + j * 28 + c4);
                acc.x = fmaf(a, m.x, acc.x); acc.y = fmaf(a, m.y, acc.y);
                acc.z = fmaf(a, m.z, acc.z); acc.w = fmaf(a, m.w, acc.w);
            }
            *(float4*)(sP + t * 28 + c4) = acc;
        }
        if (tid < 36) {
            float a = sVv[24];
            const float* bm = sBm + tid * 28;
            #pragma unroll 6
            for (int j = 0; j < 24; ++j) a = fmaf(bm[j], sVv[j], a);
            sCk[tid] = a;
        }
        __syncthreads();

        // -- (c) scores: S[q][k] = 0.125*(P[q].Bm[k] + ck[k]), 2x2 tiles, lower-tri --
        if (tid < 171) {
            const int idx = tid;
            int qi = (int)((sqrtf(8.f * idx + 1.f) - 1.f) * 0.5f);
            while ((qi + 1) * (qi + 2) / 2 <= idx) ++qi;
            while (qi * (qi + 1) / 2 > idx) --qi;
            const int ki = idx - qi * (qi + 1) / 2;
            const int q0 = qi * 2, k0 = ki * 2;
            const float* Pq0 = sP + q0 * 28;
            const float* Pq1 = Pq0 + 28;
            const float* Bk0 = sBm + k0 * 28;
            const float* Bk1 = Bk0 + 28;
            float4 a00 = make_float4(0,0,0,0), a01 = a00, a10 = a00, a11 = a00;
            #pragma unroll
            for (int j = 0; j < 28; j += 4) {
                const float4 p0 = *(const float4*)(Pq0 + j);
                const float4 p1 = *(const float4*)(Pq1 + j);
                const float4 b0 = *(const float4*)(Bk0 + j);
                const float4 b1 = *(const float4*)(Bk1 + j);
                a00.x = fmaf(p0.x, b0.x, a00.x); a00.y = fmaf(p0.y, b0.y, a00.y);
                a00.z = fmaf(p0.z, b0.z, a00.z); a00.w = fmaf(p0.w, b0.w, a00.w);
                a01.x = fmaf(p0.x, b1.x, a01.x); a01.y = fmaf(p0.y, b1.y, a01.y);
                a01.z = fmaf(p0.z, b1.z, a01.z); a01.w = fmaf(p0.w, b1.w, a01.w);
                a10.x = fmaf(p1.x, b0.x, a10.x); a10.y = fmaf(p1.y, b0.y, a10.y);
                a10.z = fmaf(p1.z, b0.z, a10.z); a10.w = fmaf(p1.w, b0.w, a10.w);
                a11.x = fmaf(p1.x, b1.x, a11.x); a11.y = fmaf(p1.y, b1.y, a11.y);
                a11.z = fmaf(p1.z, b1.z, a11.z); a11.w = fmaf(p1.w, b1.w, a11.w);
            }
            const float ck0 = sCk[k0], ck1 = sCk[k0 + 1];
            sS[q0 * 40 + k0]           = 0.125f * (a00.x + a00.y + a00.z + a00.w + ck0);
            sS[q0 * 40 + k0 + 1]       = 0.125f * (a01.x + a01.y + a01.z + a01.w + ck1);
            sS[(q0 + 1) * 40 + k0]     = 0.125f * (a10.x + a10.y + a10.z + a10.w + ck0);
            sS[(q0 + 1) * 40 + k0 + 1] = 0.125f * (a11.x + a11.y + a11.z + a11.w + ck1);
        }
        __syncthreads();

        // -- (d) softmax per row (causal length q+1), warp per row --
        {
            const int warp = tid >> 5, lane = tid & 31;
            for (int q = warp; q < T_; q += 8) {
                float m = -1e30f;
                for (int k = lane; k <= q; k += 32) m = fmaxf(m, sS[q * 40 + k]);
                #pragma unroll
                for (int o = 16; o; o >>= 1) m = fmaxf(m, __shfl_xor_sync(0xffffffffu, m, o));
                float ssum = 0.0f;
                for (int k = lane; k <= q; k += 32) {
                    const float e = __expf(sS[q * 40 + k] - m);
                    sS[q * 40 + k] = e;
                    ssum += e;
                }
                #pragma unroll
                for (int o = 16; o; o >>= 1) ssum += __shfl_xor_sync(0xffffffffu, ssum, o);
                const float inv = 1.0f / ssum;
                for (int k = lane; k <= q; k += 32) sS[q * 40 + k] *= inv;
            }
        }
        __syncthreads();

        // -- (e) ctx[q][col+e] += sum_k P[q][k] * Vh[k][col+e]  (float2 per thread) --
        if (tid < 144) {
            const int q  = tid >> 2;
            const int ep = (tid & 3) * 2;
            const int cc = col + ep;
            float a0 = 0.f, a1 = 0.f;
            for (int k = 0; k <= q; ++k) {
                const float  p = sS[q * 40 + k];
                const float2 v = *(const float2*)(sVh + k * 68 + cc);
                a0 = fmaf(p, v.x, a0);
                a1 = fmaf(p, v.y, a1);
            }
            sCtx[q * 68 + cc]     += a0;
            sCtx[q * 68 + cc + 1] += a1;
        }
        __syncthreads();
    }

    // ---------------- Phase 3: load Wo^T (overwrites M/P region) ----------------
    for (int i = tid; i < 64 * 16; i += 256) {
        const int r  = i >> 4;
        const int c4 = (i & 15) * 4;
        const float4 w = *(const float4*)(Wo + r * 64 + c4);
        sWT[(c4 + 0) * 68 + r] = w.x;
        sWT[(c4 + 1) * 68 + r] = w.y;
        sWT[(c4 + 2) * 68 + r] = w.z;
        sWT[(c4 + 3) * 68 + r] = w.w;
    }
    __syncthreads();

    // ---------------- Phase 4: out = ctx @ Wo^T + bo + X  (into sVh) ----------------
    float* sOut = sVh;
    for (int i = tid; i < 18 * 16; i += 256) {
        const int t  = (i >> 4) * 2;
        const int c0 = (i & 15) * 4;
        const float4 b4 = *(const float4*)(sVec + 64 + c0);
        float4 a0 = b4, a1 = b4;
        #pragma unroll 8
        for (int e = 0; e < 64; ++e) {
            const float4 w  = *(const float4*)(sWT + e * 68 + c0);
            const float  c0v = sCtx[t * 68 + e];
            const float  c1v = sCtx[(t + 1) * 68 + e];
            a0.x = fmaf(c0v, w.x, a0.x); a0.y = fmaf(c0v, w.y, a0.y);
            a0.z = fmaf(c0v, w.z, a0.z); a0.w = fmaf(c0v, w.w, a0.w);
            a1.x = fmaf(c1v, w.x, a1.x); a1.y = fmaf(c1v, w.y, a1.y);
            a1.z = fmaf(c1v, w.z, a1.z); a1.w = fmaf(c1v, w.w, a1.w);
        }
        const float4 x0 = *(const float4*)(X + base + t * rstride + c0);
        const float4 x1 = *(const float4*)(X + base + (t + 1) * rstride + c0);
        a0.x += x0.x; a0.y += x0.y; a0.z += x0.z; a0.w += x0.w;
        a1.x += x1.x; a1.y += x1.y; a1.z += x1.z; a1.w += x1.w;
        *(float4*)(sOut + t * 68 + c0)       = a0;
        *(float4*)(sOut + (t + 1) * 68 + c0) = a1;
    }
    __syncthreads();

    // ---------------- Phase 5: LayerNorm + store ----------------
    {
        const int warp = tid >> 5, lane = tid & 31;
        for (int t = warp; t < T_; t += 8) {
            const float x0 = sOut[t * 68 + lane];
            const float x1 = sOut[t * 68 + 32 + lane];
            float s  = x0 + x1;
            float s2 = x0 * x0 + x1 * x1;
            #pragma unroll
            for (int o = 16; o; o >>= 1) {
                s  += __shfl_xor_sync(0xffffffffu, s,  o);
                s2 += __shfl_xor_sync(0xffffffffu, s2, o);
            }
            const float mu   = s * (1.0f / 64.0f);
            const float var  = s2 * (1.0f / 64.0f) - mu * mu;
            const float rstd = rsqrtf(var + LNEPS);
            float* outp = Out + base + t * rstride;
            outp[lane]      = (x0 - mu) * rstd * sVec[128 + lane]      + sVec[192 + lane];
            outp[32 + lane] = (x1 - mu) * rstd * sVec[128 + 32 + lane] + sVec[192 + 32 + lane];
        }
    }
}

extern "C" void kernel_launch(void* const* d_in, const int* in_sizes, int n_in,
                              void* d_out, int out_size) {
    (void)in_sizes; (void)n_in; (void)out_size;
    setup_kernel<<<1, 672>>>((const float*)d_in[8],  (const float*)d_in[9],
                             (const float*)d_in[10], (const float*)d_in[11]);
    cudaFuncSetAttribute(fused_attn_kernel,
                         cudaFuncAttributeMaxDynamicSharedMemorySize, SMEM_BYTES);
    fused_attn_kernel<<<B_ * NN_, 256, SMEM_BYTES>>>(
        (const float*)d_in[0],  (const float*)d_in[1],
        (const float*)d_in[2],  (const float*)d_in[3],
        (const float*)d_in[4],  (const float*)d_in[5],
        (const float*)d_in[6],  (const float*)d_in[7],
        (const float*)d_in[12], (const float*)d_in[13],
        (float*)d_out);
}